// round 1
// baseline (speedup 1.0000x reference)
#include <cuda_runtime.h>
#include <math.h>
#include <stdint.h>

#define BB 16
#define NN 4096
#define BN (BB*NN)
#define NIN 128
#define NODE_IN 256
#define XIN 384
#define HIDF 256
#define HIDA 128
#define OUTN 128
#define NH 4
#define TILE_M 32
#define THREADS 256
#define HA_STRIDE 132

// scratch (device globals; no allocation allowed)
__device__ float g_logits[(size_t)BN * NH];
__device__ float g_stats[BB * NH * 2];
__device__ float g_part[8 * BB * OUTN];

__device__ __forceinline__ int mask_mode(const void* mask) {
    unsigned w = *(const unsigned*)mask;      // mask[0,0] is always true (prefix mask)
    if (w == 1u) return 0;                    // int32
    if (w == 0x3f800000u) return 1;           // float32
    return 2;                                 // uint8 / bool bytes
}
__device__ __forceinline__ bool mask_at(const void* mask, int idx, int mode) {
    if (mode == 0) return ((const int*)mask)[idx] != 0;
    if (mode == 1) return ((const float*)mask)[idx] != 0.0f;
    return ((const unsigned char*)mask)[idx] != 0;
}

extern __shared__ float smem[];

__global__ void __launch_bounds__(THREADS, 1) nb_main_kernel(
    const float* __restrict__ nodes, const float* __restrict__ pooled_edges,
    const void* __restrict__ mask,
    const float* __restrict__ globs, const float* __restrict__ ctxt,
    const float* __restrict__ ln_g, const float* __restrict__ ln_b,
    const float* __restrict__ fw1, const float* __restrict__ fb1,
    const float* __restrict__ fw2, const float* __restrict__ fb2,
    const float* __restrict__ aw1, const float* __restrict__ ab1,
    const float* __restrict__ aw2, const float* __restrict__ ab2,
    float* __restrict__ out)
{
    float* xin_s = smem;                       // [32][384]
    float* w1s   = xin_s + TILE_M * XIN;       // [32][256] (reused for fw2 tiles)
    float* was   = w1s + 32 * HIDF;            // [32][128]
    float* h_s   = was + 32 * HIDA;            // [32][256]
    float* ha_s  = h_s + TILE_M * HIDF;        // [32][132] padded vs bank conflicts

    const int tid = threadIdx.x;
    const int b  = blockIdx.x / (NN / TILE_M);
    const int n0 = (blockIdx.x % (NN / TILE_M)) * TILE_M;

    // ---------------- Phase 0: LayerNorm + context concat -> xin_s ----------------
    {
        int wid = tid >> 5, lid = tid & 31;
        for (int m = wid; m < TILE_M; m += 8) {
            int n = n0 + m;
            const float* np = nodes + (size_t)(b * NN + n) * NIN;
            const float* pp = pooled_edges + (size_t)(b * NN + n) * NIN;
            float v[8];
            float s = 0.f, sq = 0.f;
            #pragma unroll
            for (int i = 0; i < 8; i++) {
                int j = lid + 32 * i;
                v[i] = (j < NIN) ? np[j] : pp[j - NIN];
                s  += v[i];
                sq += v[i] * v[i];
            }
            #pragma unroll
            for (int o = 16; o; o >>= 1) {
                s  += __shfl_xor_sync(0xffffffffu, s, o);
                sq += __shfl_xor_sync(0xffffffffu, sq, o);
            }
            float mu  = s * (1.0f / NODE_IN);
            float var = sq * (1.0f / NODE_IN) - mu * mu;
            float rs  = rsqrtf(var + 1e-5f);
            #pragma unroll
            for (int i = 0; i < 8; i++) {
                int j = lid + 32 * i;
                xin_s[m * XIN + j] = (v[i] - mu) * rs * ln_g[j] + ln_b[j];
            }
            #pragma unroll
            for (int i = 0; i < 4; i++) {
                int j = lid + 32 * i;
                xin_s[m * XIN + NODE_IN + j] = (j < 64) ? globs[b * 64 + j]
                                                        : ctxt[b * 64 + (j - 64)];
            }
        }
    }
    __syncthreads();

    const int tx = tid & 31, ty = tid >> 5;

    // ---------------- Phase 1: xin @ fw1 (+lrelu) and xin @ aw1 (+lrelu) ----------
    float acc[4][8];
    float acca[4][4];
    #pragma unroll
    for (int i = 0; i < 4; i++) {
        #pragma unroll
        for (int j = 0; j < 8; j++) acc[i][j] = 0.f;
        #pragma unroll
        for (int j = 0; j < 4; j++) acca[i][j] = 0.f;
    }

    #pragma unroll 1
    for (int kt = 0; kt < XIN / 32; kt++) {
        #pragma unroll
        for (int r = 0; r < 8; r++) {
            int off = tid * 4 + r * 1024;
            *(float4*)&w1s[off] = *(const float4*)&fw1[(size_t)kt * 32 * HIDF + off];
        }
        #pragma unroll
        for (int r = 0; r < 4; r++) {
            int off = tid * 4 + r * 1024;
            *(float4*)&was[off] = *(const float4*)&aw1[(size_t)kt * 32 * HIDA + off];
        }
        __syncthreads();
        #pragma unroll
        for (int kk = 0; kk < 32; kk += 4) {
            float4 xq[4];
            #pragma unroll
            for (int i = 0; i < 4; i++)
                xq[i] = *(const float4*)&xin_s[(ty + 8 * i) * XIN + kt * 32 + kk];
            #pragma unroll
            for (int u = 0; u < 4; u++) {
                const float* wr  = &w1s[(kk + u) * HIDF];
                const float* war = &was[(kk + u) * HIDA];
                #pragma unroll
                for (int j = 0; j < 8; j++) {
                    float wv = wr[tx + 32 * j];
                    #pragma unroll
                    for (int i = 0; i < 4; i++)
                        acc[i][j] += ((const float*)&xq[i])[u] * wv;
                }
                #pragma unroll
                for (int j = 0; j < 4; j++) {
                    float wv = war[tx + 32 * j];
                    #pragma unroll
                    for (int i = 0; i < 4; i++)
                        acca[i][j] += ((const float*)&xq[i])[u] * wv;
                }
            }
        }
        __syncthreads();
    }

    #pragma unroll
    for (int i = 0; i < 4; i++) {
        int m = ty + 8 * i;
        #pragma unroll
        for (int j = 0; j < 8; j++) {
            int c = tx + 32 * j;
            float v = acc[i][j] + fb1[c];
            h_s[m * HIDF + c] = (v > 0.f) ? v : 0.01f * v;
        }
        #pragma unroll
        for (int j = 0; j < 4; j++) {
            int c = tx + 32 * j;
            float v = acca[i][j] + ab1[c];
            ha_s[m * HA_STRIDE + c] = (v > 0.f) ? v : 0.01f * v;
        }
    }
    __syncthreads();

    // ---------------- Phase 2: h @ fw2 ----------------
    float acc3[4][4];
    #pragma unroll
    for (int i = 0; i < 4; i++)
        #pragma unroll
        for (int j = 0; j < 4; j++) acc3[i][j] = 0.f;

    #pragma unroll 1
    for (int kt = 0; kt < HIDF / 32; kt++) {
        #pragma unroll
        for (int r = 0; r < 4; r++) {
            int off = tid * 4 + r * 1024;
            *(float4*)&w1s[off] = *(const float4*)&fw2[(size_t)kt * 32 * OUTN + off];
        }
        __syncthreads();
        #pragma unroll
        for (int kk = 0; kk < 32; kk += 4) {
            float4 hq[4];
            #pragma unroll
            for (int i = 0; i < 4; i++)
                hq[i] = *(const float4*)&h_s[(ty + 8 * i) * HIDF + kt * 32 + kk];
            #pragma unroll
            for (int u = 0; u < 4; u++) {
                const float* wr = &w1s[(kk + u) * OUTN];
                #pragma unroll
                for (int j = 0; j < 4; j++) {
                    float wv = wr[tx + 32 * j];
                    #pragma unroll
                    for (int i = 0; i < 4; i++)
                        acc3[i][j] += ((const float*)&hq[i])[u] * wv;
                }
            }
        }
        __syncthreads();
    }

    const int mode = mask_mode(mask);

    // ---------------- attn layer 2 (tiny): ha @ aw2 -> logits ----------------
    if (tid < TILE_M * NH) {
        int m = tid >> 2, h = tid & 3;
        float a4 = ab2[h];
        #pragma unroll 4
        for (int k = 0; k < HIDA; k++)
            a4 += ha_s[m * HA_STRIDE + k] * aw2[k * NH + h];
        int n = n0 + m;
        bool valid = mask_at(mask, b * NN + n, mode);
        g_logits[((size_t)b * NN + n) * NH + h] = valid ? a4 : -INFINITY;
    }

    // ---------------- feat epilogue: mask, residual, store new_nodes --------------
    #pragma unroll
    for (int i = 0; i < 4; i++) {
        int m = ty + 8 * i;
        int n = n0 + m;
        bool valid = mask_at(mask, b * NN + n, mode);
        size_t base = ((size_t)b * NN + n) * OUTN;
        #pragma unroll
        for (int j = 0; j < 4; j++) {
            int c = tx + 32 * j;
            float f = acc3[i][j] + fb2[c];
            out[base + c] = (valid ? f : 0.0f) + nodes[base + c];
        }
    }
}

// per (b,h): max and sum(exp) over N logits
__global__ void nb_softmax_stats_kernel() {
    __shared__ float red[256];
    int bh = blockIdx.x;
    int tid = threadIdx.x;
    const float* lp = g_logits + (size_t)(bh >> 2) * NN * NH + (bh & 3);
    float m = -INFINITY;
    for (int n = tid; n < NN; n += 256) m = fmaxf(m, lp[(size_t)n * NH]);
    red[tid] = m;
    __syncthreads();
    for (int o = 128; o; o >>= 1) {
        if (tid < o) red[tid] = fmaxf(red[tid], red[tid + o]);
        __syncthreads();
    }
    float gmax = red[0];
    __syncthreads();
    float s = 0.f;
    for (int n = tid; n < NN; n += 256) s += expf(lp[(size_t)n * NH] - gmax);
    red[tid] = s;
    __syncthreads();
    for (int o = 128; o; o >>= 1) {
        if (tid < o) red[tid] += red[tid + o];
        __syncthreads();
    }
    if (tid == 0) {
        g_stats[bh * 2]     = gmax;
        g_stats[bh * 2 + 1] = red[0];
    }
}

// deterministic two-stage pooled reduction: stage 1 partials per (b, chunk)
__global__ void nb_pooled_partial_kernel(const float* __restrict__ newnodes) {
    int b  = blockIdx.x;
    int ch = blockIdx.y;
    int c  = threadIdx.x;          // 128 channels
    int h  = c >> 5;
    float gmax = g_stats[(b * NH + h) * 2];
    float gsum = g_stats[(b * NH + h) * 2 + 1];
    float scale = 0.08838834764831845f / gsum;   // 1/sqrt(128)/sum
    float a0 = 0.f, a1 = 0.f;
    int n0 = ch * (NN / 8);
    for (int n = n0; n < n0 + NN / 8; n += 2) {
        float l0 = g_logits[((size_t)b * NN + n) * NH + h];
        float l1 = g_logits[((size_t)b * NN + n + 1) * NH + h];
        float w0 = expf(l0 - gmax) * scale;      // masked: l = -inf -> w = 0
        float w1 = expf(l1 - gmax) * scale;
        a0 += newnodes[((size_t)b * NN + n) * OUTN + c] * w0;
        a1 += newnodes[((size_t)b * NN + n + 1) * OUTN + c] * w1;
    }
    g_part[(ch * BB + b) * OUTN + c] = a0 + a1;
}

__global__ void nb_pooled_final_kernel(float* __restrict__ out) {
    int idx = blockIdx.x * 256 + threadIdx.x;    // 2048 total
    float s = 0.f;
    #pragma unroll
    for (int ch = 0; ch < 8; ch++) s += g_part[ch * BB * OUTN + idx];
    out[(size_t)BN * OUTN + idx] = s;
}

extern "C" void kernel_launch(void* const* d_in, const int* in_sizes, int n_in,
                              void* d_out, int out_size) {
    const float* nodes        = (const float*)d_in[0];
    const float* pooled_edges = (const float*)d_in[1];
    const void*  mask         = d_in[2];
    const float* globs        = (const float*)d_in[3];
    const float* ctxt         = (const float*)d_in[4];
    const float* ln_g         = (const float*)d_in[5];
    const float* ln_b         = (const float*)d_in[6];
    const float* fw1          = (const float*)d_in[7];
    const float* fb1          = (const float*)d_in[8];
    const float* fw2          = (const float*)d_in[9];
    const float* fb2          = (const float*)d_in[10];
    const float* aw1          = (const float*)d_in[11];
    const float* ab1          = (const float*)d_in[12];
    const float* aw2          = (const float*)d_in[13];
    const float* ab2          = (const float*)d_in[14];
    float* out = (float*)d_out;

    const int smem_bytes = (TILE_M * XIN + 32 * HIDF + 32 * HIDA +
                            TILE_M * HIDF + TILE_M * HA_STRIDE) * 4;  // 147968
    cudaFuncSetAttribute(nb_main_kernel,
                         cudaFuncAttributeMaxDynamicSharedMemorySize, smem_bytes);

    nb_main_kernel<<<BB * (NN / TILE_M), THREADS, smem_bytes>>>(
        nodes, pooled_edges, mask, globs, ctxt, ln_g, ln_b,
        fw1, fb1, fw2, fb2, aw1, ab1, aw2, ab2, out);

    nb_softmax_stats_kernel<<<BB * NH, 256>>>();

    dim3 pg(BB, 8);
    nb_pooled_partial_kernel<<<pg, OUTN>>>(out);

    nb_pooled_final_kernel<<<(BB * OUTN) / 256, 256>>>(out);
}

// round 2
// speedup vs baseline: 2.1801x; 2.1801x over previous
#include <cuda_runtime.h>
#include <math.h>
#include <stdint.h>

#define BB 16
#define NN 4096
#define BN (BB*NN)
#define NIN 128
#define NODE_IN 256
#define XIN 384
#define HIDF 256
#define HIDA 128
#define NTOT 384
#define OUTN 128
#define NH 4
#define TM 64
#define THREADS 256

#define XSTR 388   // % 32 == 4 -> conflict-free A frags
#define WSTR 392   // % 32 == 8 -> conflict-free B frags
#define HSTR 260   // % 32 == 4
#define HASTR 132

// scratch (device globals; no allocation allowed)
__device__ float g_logits[(size_t)BN * NH];
__device__ float g_stats[BB * NH * 2];
__device__ float g_part[8 * BB * OUTN];

__device__ __forceinline__ int mask_mode(const void* mask) {
    unsigned w = *(const unsigned*)mask;      // mask[0,0] is always true (prefix mask)
    if (w == 1u) return 0;                    // int32
    if (w == 0x3f800000u) return 1;           // float32
    return 2;                                 // uint8 / bool
}
__device__ __forceinline__ bool mask_at(const void* mask, int idx, int mode) {
    if (mode == 0) return ((const int*)mask)[idx] != 0;
    if (mode == 1) return ((const float*)mask)[idx] != 0.0f;
    return ((const unsigned char*)mask)[idx] != 0;
}

__device__ __forceinline__ unsigned f2tf(float f) {
    unsigned u;
    asm("cvt.rna.tf32.f32 %0, %1;" : "=r"(u) : "f"(f));
    return u;
}

__device__ __forceinline__ void mma_tf32(float c[4],
                                         unsigned a0, unsigned a1, unsigned a2, unsigned a3,
                                         unsigned b0, unsigned b1) {
    asm volatile(
        "mma.sync.aligned.m16n8k8.row.col.f32.tf32.tf32.f32 "
        "{%0,%1,%2,%3}, {%4,%5,%6,%7}, {%8,%9}, {%0,%1,%2,%3};\n"
        : "+f"(c[0]), "+f"(c[1]), "+f"(c[2]), "+f"(c[3])
        : "r"(a0), "r"(a1), "r"(a2), "r"(a3), "r"(b0), "r"(b1));
}

extern __shared__ float smem[];

__global__ void __launch_bounds__(THREADS, 1) nb_main_kernel(
    const float* __restrict__ nodes, const float* __restrict__ pooled_edges,
    const void* __restrict__ mask,
    const float* __restrict__ globs, const float* __restrict__ ctxt,
    const float* __restrict__ ln_g, const float* __restrict__ ln_b,
    const float* __restrict__ fw1, const float* __restrict__ fb1,
    const float* __restrict__ fw2, const float* __restrict__ fb2,
    const float* __restrict__ aw1, const float* __restrict__ ab1,
    const float* __restrict__ aw2, const float* __restrict__ ab2,
    float* __restrict__ out)
{
    float* xin_s = smem;                        // [64][XSTR] tf32  (aliased by h later)
    float* w_s   = xin_s + TM * XSTR;           // 2 x [16][WSTR] tf32
    float* ha_s  = w_s + 2 * 16 * WSTR;         // [64][HASTR] fp32

    const int tid  = threadIdx.x;
    const int lane = tid & 31;
    const int wid  = tid >> 5;
    const int b  = blockIdx.x >> 6;             // 64 CTAs per batch
    const int n0 = (blockIdx.x & 63) * TM;

    // ---------------- Phase 0: LayerNorm + context concat -> xin_s (tf32) -------
    for (int m = wid; m < TM; m += 8) {
        int n = n0 + m;
        const float* np = nodes + (size_t)(b * NN + n) * NIN;
        const float* pp = pooled_edges + (size_t)(b * NN + n) * NIN;
        float v[8];
        float s = 0.f, sq = 0.f;
        #pragma unroll
        for (int i = 0; i < 8; i++) {
            int j = lane + 32 * i;
            v[i] = (j < NIN) ? np[j] : pp[j - NIN];
            s  += v[i];
            sq += v[i] * v[i];
        }
        #pragma unroll
        for (int o = 16; o; o >>= 1) {
            s  += __shfl_xor_sync(0xffffffffu, s, o);
            sq += __shfl_xor_sync(0xffffffffu, sq, o);
        }
        float mu  = s * (1.0f / NODE_IN);
        float var = sq * (1.0f / NODE_IN) - mu * mu;
        float rs  = rsqrtf(var + 1e-5f);
        #pragma unroll
        for (int i = 0; i < 8; i++) {
            int j = lane + 32 * i;
            float x = (v[i] - mu) * rs * ln_g[j] + ln_b[j];
            xin_s[m * XSTR + j] = __uint_as_float(f2tf(x));
        }
        #pragma unroll
        for (int i = 0; i < 4; i++) {
            int j = lane + 32 * i;
            float x = (j < 64) ? globs[b * 64 + j] : ctxt[b * 64 + (j - 64)];
            xin_s[m * XSTR + NODE_IN + j] = __uint_as_float(f2tf(x));
        }
    }

    // ---------------- Phase 1: C1[64x384] = xin @ [fw1|aw1], tensor cores -------
    const int wm = wid >> 2;   // 0..1  (M)
    const int wn = wid & 3;    // 0..3  (N)

    float acc[2][12][4];
    #pragma unroll
    for (int i = 0; i < 2; i++)
        #pragma unroll
        for (int j = 0; j < 12; j++)
            #pragma unroll
            for (int e = 0; e < 4; e++) acc[i][j][e] = 0.f;

    float4 stage[6];
    // prologue: LDG+STS tile 0
    #pragma unroll
    for (int p = 0; p < 6; p++) {
        int idx = tid + p * 256;
        int row = idx / 96, c4 = idx - row * 96, n = c4 * 4;
        const float* src = (n < HIDF) ? fw1 + (size_t)row * HIDF + n
                                      : aw1 + (size_t)row * HIDA + (n - HIDF);
        stage[p] = *(const float4*)src;
    }
    #pragma unroll
    for (int p = 0; p < 6; p++) {
        int idx = tid + p * 256;
        int row = idx / 96, c4 = idx - row * 96, n = c4 * 4;
        float4 t;
        t.x = __uint_as_float(f2tf(stage[p].x));
        t.y = __uint_as_float(f2tf(stage[p].y));
        t.z = __uint_as_float(f2tf(stage[p].z));
        t.w = __uint_as_float(f2tf(stage[p].w));
        *(float4*)&w_s[row * WSTR + n] = t;
    }
    __syncthreads();

    #pragma unroll 1
    for (int kt = 0; kt < XIN / 16; kt++) {
        float* wbuf = w_s + (kt & 1) * 16 * WSTR;
        if (kt + 1 < XIN / 16) {
            #pragma unroll
            for (int p = 0; p < 6; p++) {
                int idx = tid + p * 256;
                int row = idx / 96, c4 = idx - row * 96, n = c4 * 4;
                const float* src = (n < HIDF)
                    ? fw1 + (size_t)((kt + 1) * 16 + row) * HIDF + n
                    : aw1 + (size_t)((kt + 1) * 16 + row) * HIDA + (n - HIDF);
                stage[p] = *(const float4*)src;
            }
        }
        const unsigned* xp = (const unsigned*)xin_s;
        const unsigned* wp = (const unsigned*)wbuf;
        #pragma unroll
        for (int s = 0; s < 2; s++) {
            int kb = kt * 16 + s * 8 + (lane & 3);
            unsigned a[2][4];
            #pragma unroll
            for (int i = 0; i < 2; i++) {
                int rm = wm * 32 + i * 16 + (lane >> 2);
                a[i][0] = xp[rm * XSTR + kb];
                a[i][1] = xp[(rm + 8) * XSTR + kb];
                a[i][2] = xp[rm * XSTR + kb + 4];
                a[i][3] = xp[(rm + 8) * XSTR + kb + 4];
            }
            #pragma unroll
            for (int j = 0; j < 12; j++) {
                int n = wn * 96 + j * 8 + (lane >> 2);
                unsigned b0 = wp[(s * 8 + (lane & 3)) * WSTR + n];
                unsigned b1 = wp[(s * 8 + (lane & 3) + 4) * WSTR + n];
                mma_tf32(acc[0][j], a[0][0], a[0][1], a[0][2], a[0][3], b0, b1);
                mma_tf32(acc[1][j], a[1][0], a[1][1], a[1][2], a[1][3], b0, b1);
            }
        }
        if (kt + 1 < XIN / 16) {
            float* wnext = w_s + ((kt + 1) & 1) * 16 * WSTR;
            #pragma unroll
            for (int p = 0; p < 6; p++) {
                int idx = tid + p * 256;
                int row = idx / 96, c4 = idx - row * 96, n = c4 * 4;
                float4 t;
                t.x = __uint_as_float(f2tf(stage[p].x));
                t.y = __uint_as_float(f2tf(stage[p].y));
                t.z = __uint_as_float(f2tf(stage[p].z));
                t.w = __uint_as_float(f2tf(stage[p].w));
                *(float4*)&wnext[row * WSTR + n] = t;
            }
        }
        __syncthreads();
    }

    // ---- layer1 epilogue: bias + lrelu; feat -> h_s (tf32, aliases xin), attn -> ha_s
    float* h_s = xin_s;
    #pragma unroll
    for (int i = 0; i < 2; i++) {
        #pragma unroll
        for (int j = 0; j < 12; j++) {
            #pragma unroll
            for (int e = 0; e < 4; e++) {
                int m = wm * 32 + i * 16 + (lane >> 2) + ((e >> 1) * 8);
                int n = wn * 96 + j * 8 + 2 * (lane & 3) + (e & 1);
                float v = acc[i][j][e];
                if (n < HIDF) {
                    v += fb1[n];
                    v = (v > 0.f) ? v : 0.01f * v;
                    h_s[m * HSTR + n] = __uint_as_float(f2tf(v));
                } else {
                    v += ab1[n - HIDF];
                    v = (v > 0.f) ? v : 0.01f * v;
                    ha_s[m * HASTR + (n - HIDF)] = v;
                }
            }
        }
    }

    // ---------------- Phase 2: C2[64x128] = h @ fw2, tensor cores ---------------
    float acc2[2][4][4];
    #pragma unroll
    for (int i = 0; i < 2; i++)
        #pragma unroll
        for (int j = 0; j < 4; j++)
            #pragma unroll
            for (int e = 0; e < 4; e++) acc2[i][j][e] = 0.f;

    float4 st2[2];
    #pragma unroll
    for (int p = 0; p < 2; p++) {
        int idx = tid + p * 256;
        int row = idx >> 5, n = (idx & 31) * 4;
        st2[p] = *(const float4*)(fw2 + (size_t)row * OUTN + n);
    }
    #pragma unroll
    for (int p = 0; p < 2; p++) {
        int idx = tid + p * 256;
        int row = idx >> 5, n = (idx & 31) * 4;
        float4 t;
        t.x = __uint_as_float(f2tf(st2[p].x));
        t.y = __uint_as_float(f2tf(st2[p].y));
        t.z = __uint_as_float(f2tf(st2[p].z));
        t.w = __uint_as_float(f2tf(st2[p].w));
        *(float4*)&w_s[row * WSTR + n] = t;
    }
    __syncthreads();   // covers h_s/ha_s writes + w2 tile 0

    #pragma unroll 1
    for (int kt = 0; kt < HIDF / 16; kt++) {
        float* wbuf = w_s + (kt & 1) * 16 * WSTR;
        if (kt + 1 < HIDF / 16) {
            #pragma unroll
            for (int p = 0; p < 2; p++) {
                int idx = tid + p * 256;
                int row = idx >> 5, n = (idx & 31) * 4;
                st2[p] = *(const float4*)(fw2 + (size_t)((kt + 1) * 16 + row) * OUTN + n);
            }
        }
        const unsigned* hp = (const unsigned*)h_s;
        const unsigned* wp = (const unsigned*)wbuf;
        #pragma unroll
        for (int s = 0; s < 2; s++) {
            int kb = kt * 16 + s * 8 + (lane & 3);
            unsigned a[2][4];
            #pragma unroll
            for (int i = 0; i < 2; i++) {
                int rm = wm * 32 + i * 16 + (lane >> 2);
                a[i][0] = hp[rm * HSTR + kb];
                a[i][1] = hp[(rm + 8) * HSTR + kb];
                a[i][2] = hp[rm * HSTR + kb + 4];
                a[i][3] = hp[(rm + 8) * HSTR + kb + 4];
            }
            #pragma unroll
            for (int j = 0; j < 4; j++) {
                int n = wn * 32 + j * 8 + (lane >> 2);
                unsigned b0 = wp[(s * 8 + (lane & 3)) * WSTR + n];
                unsigned b1 = wp[(s * 8 + (lane & 3) + 4) * WSTR + n];
                mma_tf32(acc2[0][j], a[0][0], a[0][1], a[0][2], a[0][3], b0, b1);
                mma_tf32(acc2[1][j], a[1][0], a[1][1], a[1][2], a[1][3], b0, b1);
            }
        }
        if (kt + 1 < HIDF / 16) {
            float* wnext = w_s + ((kt + 1) & 1) * 16 * WSTR;
            #pragma unroll
            for (int p = 0; p < 2; p++) {
                int idx = tid + p * 256;
                int row = idx >> 5, n = (idx & 31) * 4;
                float4 t;
                t.x = __uint_as_float(f2tf(st2[p].x));
                t.y = __uint_as_float(f2tf(st2[p].y));
                t.z = __uint_as_float(f2tf(st2[p].z));
                t.w = __uint_as_float(f2tf(st2[p].w));
                *(float4*)&wnext[row * WSTR + n] = t;
            }
        }
        __syncthreads();
    }

    const int mode = mask_mode(mask);

    // ---- layer2 epilogue: bias, mask, residual, store new_nodes ----
    #pragma unroll
    for (int i = 0; i < 2; i++) {
        #pragma unroll
        for (int j = 0; j < 4; j++) {
            #pragma unroll
            for (int e = 0; e < 4; e += 2) {
                int m = wm * 32 + i * 16 + (lane >> 2) + ((e >> 1) * 8);
                int n = wn * 32 + j * 8 + 2 * (lane & 3);
                int nd = n0 + m;
                bool valid = mask_at(mask, b * NN + nd, mode);
                size_t base = ((size_t)b * NN + nd) * OUTN + n;
                float v0 = acc2[i][j][e] + fb2[n];
                float v1 = acc2[i][j][e + 1] + fb2[n + 1];
                out[base]     = (valid ? v0 : 0.f) + nodes[base];
                out[base + 1] = (valid ? v1 : 0.f) + nodes[base + 1];
            }
        }
    }

    // ---- attn layer 2 (tiny): ha @ aw2 -> logits ----
    {
        int m = tid >> 2, h = tid & 3;
        float a4 = ab2[h];
        #pragma unroll 4
        for (int k = 0; k < HIDA; k++)
            a4 += ha_s[m * HASTR + k] * aw2[k * NH + h];
        int n = n0 + m;
        bool valid = mask_at(mask, b * NN + n, mode);
        g_logits[((size_t)b * NN + n) * NH + h] = valid ? a4 : -INFINITY;
    }
}

// per (b,h): max and sum(exp) over N logits
__global__ void nb_softmax_stats_kernel() {
    __shared__ float red[256];
    int bh = blockIdx.x;
    int tid = threadIdx.x;
    const float* lp = g_logits + (size_t)(bh >> 2) * NN * NH + (bh & 3);
    float m = -INFINITY;
    for (int n = tid; n < NN; n += 256) m = fmaxf(m, lp[(size_t)n * NH]);
    red[tid] = m;
    __syncthreads();
    for (int o = 128; o; o >>= 1) {
        if (tid < o) red[tid] = fmaxf(red[tid], red[tid + o]);
        __syncthreads();
    }
    float gmax = red[0];
    __syncthreads();
    float s = 0.f;
    for (int n = tid; n < NN; n += 256) s += expf(lp[(size_t)n * NH] - gmax);
    red[tid] = s;
    __syncthreads();
    for (int o = 128; o; o >>= 1) {
        if (tid < o) red[tid] += red[tid + o];
        __syncthreads();
    }
    if (tid == 0) {
        g_stats[bh * 2]     = gmax;
        g_stats[bh * 2 + 1] = red[0];
    }
}

// deterministic two-stage pooled reduction
__global__ void nb_pooled_partial_kernel(const float* __restrict__ newnodes) {
    int b  = blockIdx.x;
    int ch = blockIdx.y;
    int c  = threadIdx.x;
    int h  = c >> 5;
    float gmax = g_stats[(b * NH + h) * 2];
    float gsum = g_stats[(b * NH + h) * 2 + 1];
    float scale = 0.08838834764831845f / gsum;   // 1/sqrt(128)/sum
    float a0 = 0.f, a1 = 0.f;
    int n0 = ch * (NN / 8);
    for (int n = n0; n < n0 + NN / 8; n += 2) {
        float l0 = g_logits[((size_t)b * NN + n) * NH + h];
        float l1 = g_logits[((size_t)b * NN + n + 1) * NH + h];
        float w0 = expf(l0 - gmax) * scale;
        float w1 = expf(l1 - gmax) * scale;
        a0 += newnodes[((size_t)b * NN + n) * OUTN + c] * w0;
        a1 += newnodes[((size_t)b * NN + n + 1) * OUTN + c] * w1;
    }
    g_part[(ch * BB + b) * OUTN + c] = a0 + a1;
}

__global__ void nb_pooled_final_kernel(float* __restrict__ out) {
    int idx = blockIdx.x * 256 + threadIdx.x;
    float s = 0.f;
    #pragma unroll
    for (int ch = 0; ch < 8; ch++) s += g_part[ch * BB * OUTN + idx];
    out[(size_t)BN * OUTN + idx] = s;
}

extern "C" void kernel_launch(void* const* d_in, const int* in_sizes, int n_in,
                              void* d_out, int out_size) {
    const float* nodes        = (const float*)d_in[0];
    const float* pooled_edges = (const float*)d_in[1];
    const void*  mask         = d_in[2];
    const float* globs        = (const float*)d_in[3];
    const float* ctxt         = (const float*)d_in[4];
    const float* ln_g         = (const float*)d_in[5];
    const float* ln_b         = (const float*)d_in[6];
    const float* fw1          = (const float*)d_in[7];
    const float* fb1          = (const float*)d_in[8];
    const float* fw2          = (const float*)d_in[9];
    const float* fb2          = (const float*)d_in[10];
    const float* aw1          = (const float*)d_in[11];
    const float* ab1          = (const float*)d_in[12];
    const float* aw2          = (const float*)d_in[13];
    const float* ab2          = (const float*)d_in[14];
    float* out = (float*)d_out;

    const int smem_bytes = (TM * XSTR + 2 * 16 * WSTR + TM * HASTR) * 4;  // 183296
    cudaFuncSetAttribute(nb_main_kernel,
                         cudaFuncAttributeMaxDynamicSharedMemorySize, smem_bytes);

    nb_main_kernel<<<BB * (NN / TM), THREADS, smem_bytes>>>(
        nodes, pooled_edges, mask, globs, ctxt, ln_g, ln_b,
        fw1, fb1, fw2, fb2, aw1, ab1, aw2, ab2, out);

    nb_softmax_stats_kernel<<<BB * NH, 256>>>();

    dim3 pg(BB, 8);
    nb_pooled_partial_kernel<<<pg, OUTN>>>(out);

    nb_pooled_final_kernel<<<(BB * OUTN) / 256, 256>>>(out);
}

// round 5
// speedup vs baseline: 2.5141x; 1.1532x over previous
#include <cuda_runtime.h>
#include <math.h>
#include <stdint.h>

#define BB 16
#define NN 4096
#define BN (BB*NN)
#define NIN 128
#define NODE_IN 256
#define HIDF 256
#define HIDA 128
#define OUTN 128
#define NH 4
#define NTOT 384
#define KTOT 256
#define TM 64
#define THREADS 256

#define XSTR 260   // % 32 == 4 -> conflict-free A frags
#define WSTR 392   // % 32 == 8 -> conflict-free B frags
#define HASTR 132

// ---------------- device scratch (no allocation allowed) ----------------
__device__ float g_w1[KTOT * NTOT];      // [k][n] (fw1|aw1), tf32-rounded
__device__ float g_w2[KTOT * OUTN];      // [k][n] fw2, tf32-rounded
__device__ float g_c1[BB * NTOT];        // per-batch context bias (exact fp32)
__device__ float g_logits[(size_t)BN * NH];
__device__ float g_stats[BB * NH * 2];
__device__ float g_part[8 * BB * OUTN];

// ---------------- helpers ----------------
__device__ __forceinline__ uint32_t smem_u32(const void* p) {
    uint32_t a;
    asm("{ .reg .u64 t; cvta.to.shared.u64 t, %1; cvt.u32.u64 %0, t; }" : "=r"(a) : "l"(p));
    return a;
}
__device__ __forceinline__ unsigned f2tf(float f) {
    unsigned u;
    asm("cvt.rna.tf32.f32 %0, %1;" : "=r"(u) : "f"(f));
    return u;
}
__device__ __forceinline__ void cp16(uint32_t dst, const void* src) {
    asm volatile("cp.async.cg.shared.global [%0], [%1], 16;" :: "r"(dst), "l"(src));
}
#define CP_COMMIT() asm volatile("cp.async.commit_group;" ::: "memory")
#define CP_WAIT(n)  asm volatile("cp.async.wait_group %0;" :: "n"(n) : "memory")

__device__ __forceinline__ void mma_tf32(float c[4],
                                         unsigned a0, unsigned a1, unsigned a2, unsigned a3,
                                         unsigned b0, unsigned b1) {
    asm volatile(
        "mma.sync.aligned.m16n8k8.row.col.f32.tf32.tf32.f32 "
        "{%0,%1,%2,%3}, {%4,%5,%6,%7}, {%8,%9}, {%0,%1,%2,%3};\n"
        : "+f"(c[0]), "+f"(c[1]), "+f"(c[2]), "+f"(c[3])
        : "r"(a0), "r"(a1), "r"(a2), "r"(a3), "r"(b0), "r"(b1));
}

__device__ __forceinline__ int mask_mode(const void* mask) {
    unsigned w = *(const unsigned*)mask;      // mask[0,0] is always true (prefix mask)
    if (w == 1u) return 0;                    // int32
    if (w == 0x3f800000u) return 1;           // float32
    return 2;                                 // uint8 / bool
}
__device__ __forceinline__ bool mask_at(const void* mask, int idx, int mode) {
    if (mode == 0) return ((const int*)mask)[idx] != 0;
    if (mode == 1) return ((const float*)mask)[idx] != 0.0f;
    return ((const unsigned char*)mask)[idx] != 0;
}

// ---------------- prep: tf32 weights + per-batch context bias ----------------
__global__ void nb_prep_kernel(const float* __restrict__ fw1, const float* __restrict__ aw1,
                               const float* __restrict__ fw2,
                               const float* __restrict__ globs, const float* __restrict__ ctxt) {
    int idx = blockIdx.x * 256 + threadIdx.x;
    if (idx < KTOT * NTOT) {
        int k = idx / NTOT, n = idx - k * NTOT;
        float v = (n < HIDF) ? fw1[k * HIDF + n] : aw1[k * HIDA + (n - HIDF)];
        g_w1[idx] = __uint_as_float(f2tf(v));
    } else if (idx < KTOT * NTOT + KTOT * OUTN) {
        int j = idx - KTOT * NTOT;
        g_w2[j] = __uint_as_float(f2tf(fw2[j]));
    } else if (idx < KTOT * NTOT + KTOT * OUTN + BB * NTOT) {
        int j = idx - (KTOT * NTOT + KTOT * OUTN);
        int b = j / NTOT, n = j - b * NTOT;
        float s = 0.f;
        #pragma unroll 4
        for (int t = 0; t < 128; t++) {
            float hl = (t < 64) ? globs[b * 64 + t] : ctxt[b * 64 + (t - 64)];
            float w  = (n < HIDF) ? fw1[(NODE_IN + t) * HIDF + n]
                                  : aw1[(NODE_IN + t) * HIDA + (n - HIDF)];
            s += hl * w;
        }
        g_c1[j] = s;
    }
}

// ---------------- main fused kernel ----------------
extern __shared__ float smem[];

__global__ void __launch_bounds__(THREADS, 1) nb_main_kernel(
    const float* __restrict__ nodes, const float* __restrict__ pooled_edges,
    const void* __restrict__ mask,
    const float* __restrict__ ln_g, const float* __restrict__ ln_b,
    const float* __restrict__ fb1, const float* __restrict__ ab1,
    const float* __restrict__ aw2, const float* __restrict__ ab2,
    const float* __restrict__ fb2,
    float* __restrict__ out)
{
    float* xin_s = smem;                       // [64][260] tf32 (h aliases after L1)
    float* w_s   = xin_s + TM * XSTR;          // 2 x [32][392]
    float* ha_s  = w_s + 2 * 32 * WSTR;        // [64][132] fp32

    const int tid  = threadIdx.x;
    const int lane = tid & 31;
    const int wid  = tid >> 5;
    const int b  = blockIdx.x >> 6;            // 64 CTAs per batch
    const int n0 = (blockIdx.x & 63) * TM;

    const uint32_t w_sa = smem_u32(w_s);

    // prefetch layer-1 weight tile 0 (overlaps LayerNorm)
    // tile = 32 rows x 384 floats = 3072 x 16B chunks = 12 per thread
    {
        #pragma unroll
        for (int p = 0; p < 12; p++) {
            int q = tid + p * 256;
            int row = q / 96, c16 = q - row * 96;
            cp16(w_sa + (row * WSTR + c16 * 4) * 4,
                 g_w1 + (size_t)row * NTOT + c16 * 4);
        }
        CP_COMMIT();
    }

    // -------- Phase 0: LayerNorm -> xin_s (tf32, K=256) --------
    for (int m = wid; m < TM; m += 8) {
        const float* np = nodes + (size_t)(b * NN + n0 + m) * NIN;
        const float* pp = pooled_edges + (size_t)(b * NN + n0 + m) * NIN;
        float v[8];
        float s = 0.f, sq = 0.f;
        #pragma unroll
        for (int i = 0; i < 8; i++) {
            int j = lane + 32 * i;
            v[i] = (i < 4) ? np[j] : pp[j - NIN];
            s  += v[i];
            sq += v[i] * v[i];
        }
        #pragma unroll
        for (int o = 16; o; o >>= 1) {
            s  += __shfl_xor_sync(0xffffffffu, s, o);
            sq += __shfl_xor_sync(0xffffffffu, sq, o);
        }
        float mu  = s * (1.0f / NODE_IN);
        float var = sq * (1.0f / NODE_IN) - mu * mu;
        float rs  = rsqrtf(var + 1e-5f);
        #pragma unroll
        for (int i = 0; i < 8; i++) {
            int j = lane + 32 * i;
            float x = (v[i] - mu) * rs * ln_g[j] + ln_b[j];
            xin_s[m * XSTR + j] = __uint_as_float(f2tf(x));
        }
    }

    const int wm = wid >> 2;   // 0..1 (M)
    const int wn = wid & 3;    // 0..3 (N)

    // -------- Layer 1: C1[64x384] = X @ W1  (8 k-tiles of 32) --------
    float acc[2][12][4];
    #pragma unroll
    for (int i = 0; i < 2; i++)
        #pragma unroll
        for (int j = 0; j < 12; j++)
            #pragma unroll
            for (int e = 0; e < 4; e++) acc[i][j][e] = 0.f;

    #pragma unroll 1
    for (int kt = 0; kt < 8; kt++) {
        if (kt + 1 < 8) {
            uint32_t base = w_sa + ((kt + 1) & 1) * 32 * WSTR * 4;
            #pragma unroll
            for (int p = 0; p < 12; p++) {
                int q = tid + p * 256;
                int row = q / 96, c16 = q - row * 96;
                cp16(base + (row * WSTR + c16 * 4) * 4,
                     g_w1 + (size_t)((kt + 1) * 32 + row) * NTOT + c16 * 4);
            }
            CP_COMMIT();
            CP_WAIT(1);
        } else {
            CP_WAIT(0);
        }
        __syncthreads();
        const unsigned* xp = (const unsigned*)xin_s;
        const unsigned* wp = (const unsigned*)(w_s + (kt & 1) * 32 * WSTR);
        #pragma unroll
        for (int s = 0; s < 4; s++) {
            int kl = s * 8 + (lane & 3);
            unsigned a[2][4];
            #pragma unroll
            for (int i = 0; i < 2; i++) {
                int rm = wm * 32 + i * 16 + (lane >> 2);
                a[i][0] = xp[rm * XSTR + kt * 32 + kl];
                a[i][1] = xp[(rm + 8) * XSTR + kt * 32 + kl];
                a[i][2] = xp[rm * XSTR + kt * 32 + kl + 4];
                a[i][3] = xp[(rm + 8) * XSTR + kt * 32 + kl + 4];
            }
            #pragma unroll
            for (int j = 0; j < 12; j++) {
                int n = wn * 96 + j * 8 + (lane >> 2);
                unsigned b0 = wp[kl * WSTR + n];
                unsigned b1 = wp[(kl + 4) * WSTR + n];
                mma_tf32(acc[0][j], a[0][0], a[0][1], a[0][2], a[0][3], b0, b1);
                mma_tf32(acc[1][j], a[1][0], a[1][1], a[1][2], a[1][3], b0, b1);
            }
        }
        __syncthreads();
    }

    // prefetch layer-2 weight tile 0 (overlaps epilogue-1)
    // tile = 32 rows x 128 floats = 1024 x 16B chunks = 4 per thread
    {
        #pragma unroll
        for (int p = 0; p < 4; p++) {
            int q = tid + p * 256;
            int row = q >> 5, c16 = q & 31;
            cp16(w_sa + (row * WSTR + c16 * 4) * 4,
                 g_w2 + (size_t)row * OUTN + c16 * 4);
        }
        CP_COMMIT();
    }

    // -------- epilogue 1: bias + ctx bias + lrelu; feat -> h (tf32), attn -> ha ----
    float* h_s = xin_s;
    const float* c1b = g_c1 + b * NTOT;
    #pragma unroll
    for (int i = 0; i < 2; i++) {
        #pragma unroll
        for (int j = 0; j < 12; j++) {
            #pragma unroll
            for (int e = 0; e < 4; e++) {
                int m = wm * 32 + i * 16 + (lane >> 2) + ((e >> 1) * 8);
                int n = wn * 96 + j * 8 + 2 * (lane & 3) + (e & 1);
                float v = acc[i][j][e] + c1b[n];
                if (n < HIDF) {
                    v += fb1[n];
                    v = (v > 0.f) ? v : 0.01f * v;
                    h_s[m * XSTR + n] = __uint_as_float(f2tf(v));
                } else {
                    v += ab1[n - HIDF];
                    v = (v > 0.f) ? v : 0.01f * v;
                    ha_s[m * HASTR + (n - HIDF)] = v;
                }
            }
        }
    }

    // -------- Layer 2: C2[64x128] = h @ W2  (8 k-tiles of 32) --------
    float acc2[2][4][4];
    #pragma unroll
    for (int i = 0; i < 2; i++)
        #pragma unroll
        for (int j = 0; j < 4; j++)
            #pragma unroll
            for (int e = 0; e < 4; e++) acc2[i][j][e] = 0.f;

    #pragma unroll 1
    for (int kt = 0; kt < 8; kt++) {
        if (kt + 1 < 8) {
            uint32_t base = w_sa + ((kt + 1) & 1) * 32 * WSTR * 4;
            #pragma unroll
            for (int p = 0; p < 4; p++) {
                int q = tid + p * 256;
                int row = q >> 5, c16 = q & 31;
                cp16(base + (row * WSTR + c16 * 4) * 4,
                     g_w2 + (size_t)((kt + 1) * 32 + row) * OUTN + c16 * 4);
            }
            CP_COMMIT();
            CP_WAIT(1);
        } else {
            CP_WAIT(0);
        }
        __syncthreads();    // first iter: also publishes h_s/ha_s writes
        const unsigned* hp = (const unsigned*)h_s;
        const unsigned* wp = (const unsigned*)(w_s + (kt & 1) * 32 * WSTR);
        #pragma unroll
        for (int s = 0; s < 4; s++) {
            int kl = s * 8 + (lane & 3);
            unsigned a[2][4];
            #pragma unroll
            for (int i = 0; i < 2; i++) {
                int rm = wm * 32 + i * 16 + (lane >> 2);
                a[i][0] = hp[rm * XSTR + kt * 32 + kl];
                a[i][1] = hp[(rm + 8) * XSTR + kt * 32 + kl];
                a[i][2] = hp[rm * XSTR + kt * 32 + kl + 4];
                a[i][3] = hp[(rm + 8) * XSTR + kt * 32 + kl + 4];
            }
            #pragma unroll
            for (int j = 0; j < 4; j++) {
                int n = wn * 32 + j * 8 + (lane >> 2);
                unsigned b0 = wp[kl * WSTR + n];
                unsigned b1 = wp[(kl + 4) * WSTR + n];
                mma_tf32(acc2[0][j], a[0][0], a[0][1], a[0][2], a[0][3], b0, b1);
                mma_tf32(acc2[1][j], a[1][0], a[1][1], a[1][2], a[1][3], b0, b1);
            }
        }
        __syncthreads();
    }

    const int mode = mask_mode(mask);

    // -------- epilogue 2: bias, mask, residual, store new_nodes --------
    #pragma unroll
    for (int i = 0; i < 2; i++) {
        #pragma unroll
        for (int j = 0; j < 4; j++) {
            #pragma unroll
            for (int e = 0; e < 4; e += 2) {
                int m = wm * 32 + i * 16 + (lane >> 2) + ((e >> 1) * 8);
                int n = wn * 32 + j * 8 + 2 * (lane & 3);
                int nd = n0 + m;
                bool valid = mask_at(mask, b * NN + nd, mode);
                size_t base = ((size_t)b * NN + nd) * OUTN + n;
                float v0 = acc2[i][j][e] + fb2[n];
                float v1 = acc2[i][j][e + 1] + fb2[n + 1];
                out[base]     = (valid ? v0 : 0.f) + nodes[base];
                out[base + 1] = (valid ? v1 : 0.f) + nodes[base + 1];
            }
        }
    }

    // -------- attn layer 2 (tiny): ha @ aw2 -> logits --------
    {
        int m = tid >> 2, h = tid & 3;
        float a4 = ab2[h];
        #pragma unroll 4
        for (int k = 0; k < HIDA; k++)
            a4 += ha_s[m * HASTR + k] * aw2[k * NH + h];
        int n = n0 + m;
        bool valid = mask_at(mask, b * NN + n, mode);
        g_logits[((size_t)b * NN + n) * NH + h] = valid ? a4 : -INFINITY;
    }
}

// ---------------- softmax stats ----------------
__global__ void nb_softmax_stats_kernel() {
    __shared__ float red[256];
    int bh = blockIdx.x;
    int tid = threadIdx.x;
    const float* lp = g_logits + (size_t)(bh >> 2) * NN * NH + (bh & 3);
    float m = -INFINITY;
    for (int n = tid; n < NN; n += 256) m = fmaxf(m, lp[(size_t)n * NH]);
    red[tid] = m;
    __syncthreads();
    for (int o = 128; o; o >>= 1) {
        if (tid < o) red[tid] = fmaxf(red[tid], red[tid + o]);
        __syncthreads();
    }
    float gmax = red[0];
    __syncthreads();
    float s = 0.f;
    for (int n = tid; n < NN; n += 256) s += expf(lp[(size_t)n * NH] - gmax);
    red[tid] = s;
    __syncthreads();
    for (int o = 128; o; o >>= 1) {
        if (tid < o) red[tid] += red[tid + o];
        __syncthreads();
    }
    if (tid == 0) {
        g_stats[bh * 2]     = gmax;
        g_stats[bh * 2 + 1] = red[0];
    }
}

// ---------------- deterministic two-stage pooled reduction ----------------
__global__ void nb_pooled_partial_kernel(const float* __restrict__ newnodes) {
    int b  = blockIdx.x;
    int ch = blockIdx.y;
    int c  = threadIdx.x;
    int h  = c >> 5;
    float gmax = g_stats[(b * NH + h) * 2];
    float gsum = g_stats[(b * NH + h) * 2 + 1];
    float scale = 0.08838834764831845f / gsum;   // 1/sqrt(128)/sum
    float a0 = 0.f, a1 = 0.f;
    int n0 = ch * (NN / 8);
    for (int n = n0; n < n0 + NN / 8; n += 2) {
        float l0 = g_logits[((size_t)b * NN + n) * NH + h];
        float l1 = g_logits[((size_t)b * NN + n + 1) * NH + h];
        float w0 = expf(l0 - gmax) * scale;
        float w1 = expf(l1 - gmax) * scale;
        a0 += newnodes[((size_t)b * NN + n) * OUTN + c] * w0;
        a1 += newnodes[((size_t)b * NN + n + 1) * OUTN + c] * w1;
    }
    g_part[(ch * BB + b) * OUTN + c] = a0 + a1;
}

__global__ void nb_pooled_final_kernel(float* __restrict__ out) {
    int idx = blockIdx.x * 256 + threadIdx.x;
    float s = 0.f;
    #pragma unroll
    for (int ch = 0; ch < 8; ch++) s += g_part[ch * BB * OUTN + idx];
    out[(size_t)BN * OUTN + idx] = s;
}

extern "C" void kernel_launch(void* const* d_in, const int* in_sizes, int n_in,
                              void* d_out, int out_size) {
    const float* nodes        = (const float*)d_in[0];
    const float* pooled_edges = (const float*)d_in[1];
    const void*  mask         = d_in[2];
    const float* globs        = (const float*)d_in[3];
    const float* ctxt         = (const float*)d_in[4];
    const float* ln_g         = (const float*)d_in[5];
    const float* ln_b         = (const float*)d_in[6];
    const float* fw1          = (const float*)d_in[7];
    const float* fb1          = (const float*)d_in[8];
    const float* fw2          = (const float*)d_in[9];
    const float* fb2          = (const float*)d_in[10];
    const float* aw1          = (const float*)d_in[11];
    const float* ab1          = (const float*)d_in[12];
    const float* aw2          = (const float*)d_in[13];
    const float* ab2          = (const float*)d_in[14];
    float* out = (float*)d_out;

    int prep_elems = KTOT * NTOT + KTOT * OUTN + BB * NTOT;
    nb_prep_kernel<<<(prep_elems + 255) / 256, 256>>>(fw1, aw1, fw2, globs, ctxt);

    const int smem_bytes = (TM * XSTR + 2 * 32 * WSTR + TM * HASTR) * 4;  // 200704
    cudaFuncSetAttribute(nb_main_kernel,
                         cudaFuncAttributeMaxDynamicSharedMemorySize, smem_bytes);
    nb_main_kernel<<<BB * (NN / TM), THREADS, smem_bytes>>>(
        nodes, pooled_edges, mask, ln_g, ln_b,
        fb1, ab1, aw2, ab2, fb2, out);

    nb_softmax_stats_kernel<<<BB * NH, 256>>>();

    dim3 pg(BB, 8);
    nb_pooled_partial_kernel<<<pg, OUTN>>>(out);

    nb_pooled_final_kernel<<<(BB * OUTN) / 256, 256>>>(out);
}

// round 6
// speedup vs baseline: 2.8428x; 1.1308x over previous
#include <cuda_runtime.h>
#include <math.h>
#include <stdint.h>

#define BB 16
#define NN 4096
#define BN (BB*NN)
#define NIN 128
#define NODE_IN 256
#define HIDF 256
#define HIDA 128
#define OUTN 128
#define NH 4
#define NTOT 384
#define KTOT 256
#define TM 64
#define THREADS 256
#define NCH 32

#define XSTR 264    // %32==8 -> conflict-free LDS.64 A frags
#define W1STR 776   // %32==8 -> conflict-free LDS.64 B frags (layer1, 768+8)
#define W2STR 264   // %32==8 (layer2, 256+8)
#define WBUF 12416  // floats per weight buffer (16*776)
#define HASTR 132

// ---------------- device scratch (no allocation allowed) ----------------
__device__ float g_w1p[128 * 768];       // packed: row=(k>>3)*4+(k&3), col=2n+((k>>2)&1)
__device__ float g_w2p[128 * 256];
__device__ float g_c1[BB * NTOT];        // per-batch context bias (exact fp32)
__device__ float g_logits[(size_t)BN * NH];
__device__ float g_stats[BB * NH * 2];
__device__ float g_part[NCH * BB * OUTN];

// ---------------- helpers ----------------
__device__ __forceinline__ uint32_t smem_u32(const void* p) {
    uint32_t a;
    asm("{ .reg .u64 t; cvta.to.shared.u64 t, %1; cvt.u32.u64 %0, t; }" : "=r"(a) : "l"(p));
    return a;
}
__device__ __forceinline__ unsigned f2tf(float f) {
    unsigned u;
    asm("cvt.rna.tf32.f32 %0, %1;" : "=r"(u) : "f"(f));
    return u;
}
__device__ __forceinline__ void cp16(uint32_t dst, const void* src) {
    asm volatile("cp.async.cg.shared.global [%0], [%1], 16;" :: "r"(dst), "l"(src));
}
#define CP_COMMIT() asm volatile("cp.async.commit_group;" ::: "memory")
#define CP_WAIT(n)  asm volatile("cp.async.wait_group %0;" :: "n"(n) : "memory")

__device__ __forceinline__ void mma_tf32(float c[4],
                                         unsigned a0, unsigned a1, unsigned a2, unsigned a3,
                                         unsigned b0, unsigned b1) {
    asm volatile(
        "mma.sync.aligned.m16n8k8.row.col.f32.tf32.tf32.f32 "
        "{%0,%1,%2,%3}, {%4,%5,%6,%7}, {%8,%9}, {%0,%1,%2,%3};\n"
        : "+f"(c[0]), "+f"(c[1]), "+f"(c[2]), "+f"(c[3])
        : "r"(a0), "r"(a1), "r"(a2), "r"(a3), "r"(b0), "r"(b1));
}

__device__ __forceinline__ int perm8(int j) {   // within-octet k-pair interleave
    return (j & ~7) | ((j & 3) << 1) | ((j >> 2) & 1);
}

__device__ __forceinline__ int mask_mode(const void* mask) {
    unsigned w = *(const unsigned*)mask;      // mask[0,0] is always true (prefix mask)
    if (w == 1u) return 0;                    // int32
    if (w == 0x3f800000u) return 1;           // float32
    return 2;                                 // uint8 / bool
}
__device__ __forceinline__ bool mask_at(const void* mask, int idx, int mode) {
    if (mode == 0) return ((const int*)mask)[idx] != 0;
    if (mode == 1) return ((const float*)mask)[idx] != 0.0f;
    return ((const unsigned char*)mask)[idx] != 0;
}

// ---------------- prep: packed tf32 weights + per-batch context bias ----------------
__global__ void nb_prep_kernel(const float* __restrict__ fw1, const float* __restrict__ aw1,
                               const float* __restrict__ fw2,
                               const float* __restrict__ globs, const float* __restrict__ ctxt) {
    int idx = blockIdx.x * 256 + threadIdx.x;
    if (idx < KTOT * NTOT) {
        int k = idx / NTOT, n = idx - k * NTOT;
        float v = (n < HIDF) ? fw1[k * HIDF + n] : aw1[k * HIDA + (n - HIDF)];
        int pos = (((k >> 3) * 4) + (k & 3)) * 768 + 2 * n + ((k >> 2) & 1);
        g_w1p[pos] = __uint_as_float(f2tf(v));
    } else if (idx < KTOT * NTOT + KTOT * OUTN) {
        int j = idx - KTOT * NTOT;
        int k = j >> 7, n = j & 127;
        int pos = (((k >> 3) * 4) + (k & 3)) * 256 + 2 * n + ((k >> 2) & 1);
        g_w2p[pos] = __uint_as_float(f2tf(fw2[j]));
    } else if (idx < KTOT * NTOT + KTOT * OUTN + BB * NTOT) {
        int j = idx - (KTOT * NTOT + KTOT * OUTN);
        int b = j / NTOT, n = j - b * NTOT;
        float s = 0.f;
        #pragma unroll 4
        for (int t = 0; t < 128; t++) {
            float hl = (t < 64) ? globs[b * 64 + t] : ctxt[b * 64 + (t - 64)];
            float w  = (n < HIDF) ? fw1[(NODE_IN + t) * HIDF + n]
                                  : aw1[(NODE_IN + t) * HIDA + (n - HIDF)];
            s += hl * w;
        }
        g_c1[j] = s;
    }
}

// ---------------- main fused kernel ----------------
extern __shared__ float smem[];

__global__ void __launch_bounds__(THREADS, 1) nb_main_kernel(
    const float* __restrict__ nodes, const float* __restrict__ pooled_edges,
    const void* __restrict__ mask,
    const float* __restrict__ ln_g, const float* __restrict__ ln_b,
    const float* __restrict__ fb1, const float* __restrict__ ab1,
    const float* __restrict__ aw2, const float* __restrict__ ab2,
    const float* __restrict__ fb2,
    float* __restrict__ out)
{
    float* xin_s = smem;                       // [64][264] tf32, k-pair packed (h aliases)
    float* w_s   = xin_s + TM * XSTR;          // 2 x WBUF
    float* ha_s  = w_s + 2 * WBUF;             // [64][132] fp32

    const int tid  = threadIdx.x;
    const int lane = tid & 31;
    const int wid  = tid >> 5;
    const int b  = blockIdx.x >> 6;            // 64 CTAs per batch
    const int n0 = (blockIdx.x & 63) * TM;

    const uint32_t w_sa = smem_u32(w_s);

    // prefetch L1 weight tile 0: 16 rows x 768 floats = 3072 chunks (12/thread)
    {
        #pragma unroll
        for (int p = 0; p < 12; p++) {
            int q = tid + p * 256;
            int row = q / 192, c16 = q - row * 192;
            cp16(w_sa + (row * W1STR + c16 * 4) * 4,
                 g_w1p + (size_t)row * 768 + c16 * 4);
        }
        CP_COMMIT();
    }

    // -------- Phase 0: LayerNorm -> xin_s (tf32, k-pair packed) --------
    for (int m = wid; m < TM; m += 8) {
        const float* np = nodes + (size_t)(b * NN + n0 + m) * NIN;
        const float* pp = pooled_edges + (size_t)(b * NN + n0 + m) * NIN;
        float v[8];
        float s = 0.f, sq = 0.f;
        #pragma unroll
        for (int i = 0; i < 8; i++) {
            int j = lane + 32 * i;
            v[i] = (i < 4) ? np[j] : pp[j - NIN];
            s  += v[i];
            sq += v[i] * v[i];
        }
        #pragma unroll
        for (int o = 16; o; o >>= 1) {
            s  += __shfl_xor_sync(0xffffffffu, s, o);
            sq += __shfl_xor_sync(0xffffffffu, sq, o);
        }
        float mu  = s * (1.0f / NODE_IN);
        float var = sq * (1.0f / NODE_IN) - mu * mu;
        float rs  = rsqrtf(var + 1e-5f);
        #pragma unroll
        for (int i = 0; i < 8; i++) {
            int j = lane + 32 * i;
            float x = (v[i] - mu) * rs * ln_g[j] + ln_b[j];
            xin_s[m * XSTR + perm8(j)] = __uint_as_float(f2tf(x));
        }
    }

    const int wm = wid >> 2;   // 0..1 (M)
    const int wn = wid & 3;    // 0..3 (N)

    // -------- Layer 1: C1[64x384] = X @ W1  (8 k-tiles of 32) --------
    float acc[2][12][4];
    #pragma unroll
    for (int i = 0; i < 2; i++)
        #pragma unroll
        for (int j = 0; j < 12; j++)
            #pragma unroll
            for (int e = 0; e < 4; e++) acc[i][j][e] = 0.f;

    #pragma unroll 1
    for (int kt = 0; kt < 8; kt++) {
        if (kt + 1 < 8) {
            uint32_t base = w_sa + ((kt + 1) & 1) * WBUF * 4;
            #pragma unroll
            for (int p = 0; p < 12; p++) {
                int q = tid + p * 256;
                int row = q / 192, c16 = q - row * 192;
                cp16(base + (row * W1STR + c16 * 4) * 4,
                     g_w1p + (size_t)((kt + 1) * 16 + row) * 768 + c16 * 4);
            }
            CP_COMMIT();
            CP_WAIT(1);
        } else {
            CP_WAIT(0);
        }
        __syncthreads();
        const float* xp = xin_s;
        const float* wp = w_s + (kt & 1) * WBUF;
        #pragma unroll
        for (int s = 0; s < 4; s++) {
            int kb = kt * 32 + s * 8 + (lane & 3) * 2;
            uint2 aL[2], aH[2];
            #pragma unroll
            for (int i = 0; i < 2; i++) {
                int rm = wm * 32 + i * 16 + (lane >> 2);
                aL[i] = *(const uint2*)(xp + rm * XSTR + kb);        // (a0, a2)
                aH[i] = *(const uint2*)(xp + (rm + 8) * XSTR + kb);  // (a1, a3)
            }
            int wrow = (s * 4 + (lane & 3)) * W1STR;
            #pragma unroll
            for (int j = 0; j < 12; j++) {
                int n = wn * 96 + j * 8 + (lane >> 2);
                uint2 bb = *(const uint2*)(wp + wrow + 2 * n);       // (b0, b1)
                mma_tf32(acc[0][j], aL[0].x, aH[0].x, aL[0].y, aH[0].y, bb.x, bb.y);
                mma_tf32(acc[1][j], aL[1].x, aH[1].x, aL[1].y, aH[1].y, bb.x, bb.y);
            }
        }
        __syncthreads();
    }

    // prefetch L2 weight tile 0: 16 rows x 256 floats = 1024 chunks (4/thread)
    {
        #pragma unroll
        for (int p = 0; p < 4; p++) {
            int q = tid + p * 256;
            int row = q >> 6, c16 = q & 63;
            cp16(w_sa + (row * W2STR + c16 * 4) * 4,
                 g_w2p + (size_t)row * 256 + c16 * 4);
        }
        CP_COMMIT();
    }

    // -------- epilogue 1: bias + ctx bias + lrelu; feat -> h (packed tf32), attn -> ha
    float* h_s = xin_s;
    const float* c1b = g_c1 + b * NTOT;
    #pragma unroll
    for (int i = 0; i < 2; i++) {
        #pragma unroll
        for (int j = 0; j < 12; j++) {
            #pragma unroll
            for (int e = 0; e < 4; e++) {
                int m = wm * 32 + i * 16 + (lane >> 2) + ((e >> 1) * 8);
                int n = wn * 96 + j * 8 + 2 * (lane & 3) + (e & 1);
                float v = acc[i][j][e] + c1b[n];
                if (n < HIDF) {
                    v += fb1[n];
                    v = (v > 0.f) ? v : 0.01f * v;
                    h_s[m * XSTR + perm8(n)] = __uint_as_float(f2tf(v));
                } else {
                    v += ab1[n - HIDF];
                    v = (v > 0.f) ? v : 0.01f * v;
                    ha_s[m * HASTR + (n - HIDF)] = v;
                }
            }
        }
    }

    // -------- Layer 2: C2[64x128] = h @ W2  (8 k-tiles of 32) --------
    float acc2[2][4][4];
    #pragma unroll
    for (int i = 0; i < 2; i++)
        #pragma unroll
        for (int j = 0; j < 4; j++)
            #pragma unroll
            for (int e = 0; e < 4; e++) acc2[i][j][e] = 0.f;

    #pragma unroll 1
    for (int kt = 0; kt < 8; kt++) {
        if (kt + 1 < 8) {
            uint32_t base = w_sa + ((kt + 1) & 1) * WBUF * 4;
            #pragma unroll
            for (int p = 0; p < 4; p++) {
                int q = tid + p * 256;
                int row = q >> 6, c16 = q & 63;
                cp16(base + (row * W2STR + c16 * 4) * 4,
                     g_w2p + (size_t)((kt + 1) * 16 + row) * 256 + c16 * 4);
            }
            CP_COMMIT();
            CP_WAIT(1);
        } else {
            CP_WAIT(0);
        }
        __syncthreads();    // first iter: also publishes h_s/ha_s writes
        const float* hp = h_s;
        const float* wp = w_s + (kt & 1) * WBUF;
        #pragma unroll
        for (int s = 0; s < 4; s++) {
            int kb = kt * 32 + s * 8 + (lane & 3) * 2;
            uint2 aL[2], aH[2];
            #pragma unroll
            for (int i = 0; i < 2; i++) {
                int rm = wm * 32 + i * 16 + (lane >> 2);
                aL[i] = *(const uint2*)(hp + rm * XSTR + kb);
                aH[i] = *(const uint2*)(hp + (rm + 8) * XSTR + kb);
            }
            int wrow = (s * 4 + (lane & 3)) * W2STR;
            #pragma unroll
            for (int j = 0; j < 4; j++) {
                int n = wn * 32 + j * 8 + (lane >> 2);
                uint2 bb = *(const uint2*)(wp + wrow + 2 * n);
                mma_tf32(acc2[0][j], aL[0].x, aH[0].x, aL[0].y, aH[0].y, bb.x, bb.y);
                mma_tf32(acc2[1][j], aL[1].x, aH[1].x, aL[1].y, aH[1].y, bb.x, bb.y);
            }
        }
        __syncthreads();
    }

    const int mode = mask_mode(mask);

    // -------- epilogue 2: bias, mask, residual, store new_nodes --------
    #pragma unroll
    for (int i = 0; i < 2; i++) {
        #pragma unroll
        for (int j = 0; j < 4; j++) {
            #pragma unroll
            for (int e = 0; e < 4; e += 2) {
                int m = wm * 32 + i * 16 + (lane >> 2) + ((e >> 1) * 8);
                int n = wn * 32 + j * 8 + 2 * (lane & 3);
                int nd = n0 + m;
                bool valid = mask_at(mask, b * NN + nd, mode);
                size_t base = ((size_t)b * NN + nd) * OUTN + n;
                float v0 = acc2[i][j][e] + fb2[n];
                float v1 = acc2[i][j][e + 1] + fb2[n + 1];
                out[base]     = (valid ? v0 : 0.f) + nodes[base];
                out[base + 1] = (valid ? v1 : 0.f) + nodes[base + 1];
            }
        }
    }

    // -------- attn layer 2 (tiny): ha @ aw2 -> logits --------
    {
        int m = tid >> 2, h = tid & 3;
        float a4 = ab2[h];
        #pragma unroll 4
        for (int k = 0; k < HIDA; k++)
            a4 += ha_s[m * HASTR + k] * aw2[k * NH + h];
        int n = n0 + m;
        bool valid = mask_at(mask, b * NN + n, mode);
        g_logits[((size_t)b * NN + n) * NH + h] = valid ? a4 : -INFINITY;
    }
}

// ---------------- softmax stats ----------------
__global__ void nb_softmax_stats_kernel() {
    __shared__ float red[256];
    int bh = blockIdx.x;
    int tid = threadIdx.x;
    const float* lp = g_logits + (size_t)(bh >> 2) * NN * NH + (bh & 3);
    float m = -INFINITY;
    for (int n = tid; n < NN; n += 256) m = fmaxf(m, lp[(size_t)n * NH]);
    red[tid] = m;
    __syncthreads();
    for (int o = 128; o; o >>= 1) {
        if (tid < o) red[tid] = fmaxf(red[tid], red[tid + o]);
        __syncthreads();
    }
    float gmax = red[0];
    __syncthreads();
    float s = 0.f;
    for (int n = tid; n < NN; n += 256) s += expf(lp[(size_t)n * NH] - gmax);
    red[tid] = s;
    __syncthreads();
    for (int o = 128; o; o >>= 1) {
        if (tid < o) red[tid] += red[tid + o];
        __syncthreads();
    }
    if (tid == 0) {
        g_stats[bh * 2]     = gmax;
        g_stats[bh * 2 + 1] = red[0];
    }
}

// ---------------- deterministic two-stage pooled reduction ----------------
// grid (BB, NCH), 256 threads: per block 128 nodes; float4 per thread, 8-way row split
__global__ void nb_pooled_partial_kernel(const float* __restrict__ newnodes) {
    __shared__ float sd[8][OUTN + 4];
    int b  = blockIdx.x;
    int ch = blockIdx.y;
    int q  = threadIdx.x & 31;        // channel quad 0..31
    int ro = threadIdx.x >> 5;        // row group 0..7
    int c4 = q * 4;
    int h  = q >> 3;
    float gmax = g_stats[(b * NH + h) * 2];
    float gsum = g_stats[(b * NH + h) * 2 + 1];
    float scale = 0.08838834764831845f / gsum;   // 1/sqrt(128)/sum
    float ax = 0.f, ay = 0.f, az = 0.f, aw = 0.f;
    int nbase = ch * (NN / NCH);
    #pragma unroll 4
    for (int r = ro; r < NN / NCH; r += 8) {
        int n = nbase + r;
        float l = g_logits[((size_t)b * NN + n) * NH + h];
        float w = expf(l - gmax) * scale;        // masked: l=-inf -> w=0
        float4 v = *(const float4*)&newnodes[((size_t)b * NN + n) * OUTN + c4];
        ax += v.x * w; ay += v.y * w; az += v.z * w; aw += v.w * w;
    }
    sd[ro][c4]     = ax;
    sd[ro][c4 + 1] = ay;
    sd[ro][c4 + 2] = az;
    sd[ro][c4 + 3] = aw;
    __syncthreads();
    if (threadIdx.x < OUTN) {
        float s = 0.f;
        #pragma unroll
        for (int r = 0; r < 8; r++) s += sd[r][threadIdx.x];
        g_part[(ch * BB + b) * OUTN + threadIdx.x] = s;
    }
}

__global__ void nb_pooled_final_kernel(float* __restrict__ out) {
    int idx = blockIdx.x * 256 + threadIdx.x;
    float s = 0.f;
    #pragma unroll
    for (int ch = 0; ch < NCH; ch++) s += g_part[ch * BB * OUTN + idx];
    out[(size_t)BN * OUTN + idx] = s;
}

extern "C" void kernel_launch(void* const* d_in, const int* in_sizes, int n_in,
                              void* d_out, int out_size) {
    const float* nodes        = (const float*)d_in[0];
    const float* pooled_edges = (const float*)d_in[1];
    const void*  mask         = d_in[2];
    const float* globs        = (const float*)d_in[3];
    const float* ctxt         = (const float*)d_in[4];
    const float* ln_g         = (const float*)d_in[5];
    const float* ln_b         = (const float*)d_in[6];
    const float* fw1          = (const float*)d_in[7];
    const float* fb1          = (const float*)d_in[8];
    const float* fw2          = (const float*)d_in[9];
    const float* fb2          = (const float*)d_in[10];
    const float* aw1          = (const float*)d_in[11];
    const float* ab1          = (const float*)d_in[12];
    const float* aw2          = (const float*)d_in[13];
    const float* ab2          = (const float*)d_in[14];
    float* out = (float*)d_out;

    int prep_elems = KTOT * NTOT + KTOT * OUTN + BB * NTOT;
    nb_prep_kernel<<<(prep_elems + 255) / 256, 256>>>(fw1, aw1, fw2, globs, ctxt);

    const int smem_bytes = (TM * XSTR + 2 * WBUF + TM * HASTR) * 4;  // 200704
    cudaFuncSetAttribute(nb_main_kernel,
                         cudaFuncAttributeMaxDynamicSharedMemorySize, smem_bytes);
    nb_main_kernel<<<BB * (NN / TM), THREADS, smem_bytes>>>(
        nodes, pooled_edges, mask, ln_g, ln_b,
        fb1, ab1, aw2, ab2, fb2, out);

    nb_softmax_stats_kernel<<<BB * NH, 256>>>();

    dim3 pg(BB, NCH);
    nb_pooled_partial_kernel<<<pg, 256>>>(out);

    nb_pooled_final_kernel<<<(BB * OUTN) / 256, 256>>>(out);
}